// round 1
// baseline (speedup 1.0000x reference)
#include <cuda_runtime.h>
#include <cstdint>

#define NROWS 4096
#define INDIM 1024
#define DDIM  2048
#define TWOD  4096
#define NGATE 8
#define OUTDIM 1024

// Scratch (allocation-free rule: __device__ globals)
__device__ float g_s[(size_t)NROWS * TWOD];    // 64 MB: masked block-sum s
__device__ float g_h2[(size_t)NROWS * DDIM];   // 32 MB: relu(s @ W2^T + b2)
__device__ int   g_perm[NROWS];
__device__ int   g_off[NGATE + 1];

// ---------------------------------------------------------------------------
// Counting sort of rows by gate id (order within a gate is irrelevant to math)
// ---------------------------------------------------------------------------
__global__ void sort_gates(const int* __restrict__ gate_ids) {
    __shared__ int cnt[NGATE];
    __shared__ int base[NGATE];
    int t = threadIdx.x;
    if (t < NGATE) cnt[t] = 0;
    __syncthreads();
    for (int i = t; i < NROWS; i += blockDim.x)
        atomicAdd(&cnt[gate_ids[i]], 1);
    __syncthreads();
    if (t == 0) {
        int a = 0;
        for (int g = 0; g < NGATE; g++) { base[g] = a; g_off[g] = a; a += cnt[g]; }
        g_off[NGATE] = a;
    }
    __syncthreads();
    for (int i = t; i < NROWS; i += blockDim.x) {
        int g = gate_ids[i];
        int p = atomicAdd(&base[g], 1);
        g_perm[p] = i;
    }
}

// ---------------------------------------------------------------------------
// Register-blocked SGEMM: Out[m, n] (+)= epi( A[m, :] . W[n, :] + bias[n] )
// BM=BN=128, BK=16, 256 threads, 8x8 per thread (two 4x4 quads at +0 / +64).
// GATE=true: rows are gathered through g_perm within gate segment blockIdx.z;
//            weights/bias offset by gate block.
// ---------------------------------------------------------------------------
constexpr int BM = 128, BN = 128, BK = 16;

template<bool GATE>
__global__ __launch_bounds__(256)
void sgemm(const float* __restrict__ A,
           const float* __restrict__ W,
           const float* __restrict__ bias,
           float* __restrict__ Out,
           int Nout, int K,
           int do_relu, int do_accum, float scale)
{
    __shared__ float As[BK][BM];
    __shared__ float Bs[BK][BN];

    int rowStart, rowEnd;
    const float* Wp = W;
    const float* bp = bias;
    if (GATE) {
        int g = blockIdx.z;
        int s0 = g_off[g], s1 = g_off[g + 1];
        rowStart = s0 + blockIdx.y * BM;
        if (rowStart >= s1) return;
        rowEnd = s1;
        Wp = W + (size_t)g * Nout * K;
        if (bp) bp = bp + (size_t)g * Nout;
    } else {
        rowStart = blockIdx.y * BM;
        rowEnd = rowStart + BM;
    }
    const int cb = blockIdx.x * BN;
    const int tid = threadIdx.x;
    const int tx = tid & 15, ty = tid >> 4;

    // Two (m, k4) load slots per thread: e4 = tid + i*256, m = e4>>2, k4 = (e4&3)*4
    int rowg[2], mfrac[2], kfrac[2];
#pragma unroll
    for (int i = 0; i < 2; i++) {
        int e4 = tid + i * 256;
        mfrac[i] = e4 >> 2;
        kfrac[i] = (e4 & 3) << 2;
        int rp = rowStart + mfrac[i];
        if (GATE) rowg[i] = (rp < rowEnd) ? g_perm[rp] : -1;
        else      rowg[i] = rp;
    }

    float acc[8][8];
#pragma unroll
    for (int i = 0; i < 8; i++)
#pragma unroll
        for (int j = 0; j < 8; j++) acc[i][j] = 0.f;

    for (int k0 = 0; k0 < K; k0 += BK) {
#pragma unroll
        for (int i = 0; i < 2; i++) {
            const int m = mfrac[i], k4 = kfrac[i];
            float4 va = make_float4(0.f, 0.f, 0.f, 0.f);
            if (!GATE || rowg[i] >= 0)
                va = *reinterpret_cast<const float4*>(A + (size_t)rowg[i] * K + k0 + k4);
            As[k4 + 0][m] = va.x; As[k4 + 1][m] = va.y;
            As[k4 + 2][m] = va.z; As[k4 + 3][m] = va.w;
            float4 vb = *reinterpret_cast<const float4*>(Wp + (size_t)(cb + m) * K + k0 + k4);
            Bs[k4 + 0][m] = vb.x; Bs[k4 + 1][m] = vb.y;
            Bs[k4 + 2][m] = vb.z; Bs[k4 + 3][m] = vb.w;
        }
        __syncthreads();
#pragma unroll
        for (int kk = 0; kk < BK; kk++) {
            float4 a0 = *reinterpret_cast<const float4*>(&As[kk][ty * 4]);
            float4 a1 = *reinterpret_cast<const float4*>(&As[kk][64 + ty * 4]);
            float4 b0 = *reinterpret_cast<const float4*>(&Bs[kk][tx * 4]);
            float4 b1 = *reinterpret_cast<const float4*>(&Bs[kk][64 + tx * 4]);
            float a[8] = {a0.x, a0.y, a0.z, a0.w, a1.x, a1.y, a1.z, a1.w};
            float b[8] = {b0.x, b0.y, b0.z, b0.w, b1.x, b1.y, b1.z, b1.w};
#pragma unroll
            for (int i = 0; i < 8; i++)
#pragma unroll
                for (int j = 0; j < 8; j++)
                    acc[i][j] = fmaf(a[i], b[j], acc[i][j]);
        }
        __syncthreads();
    }

    // Epilogue
#pragma unroll
    for (int i = 0; i < 8; i++) {
        const int m = (i < 4) ? (ty * 4 + i) : (64 + ty * 4 + (i - 4));
        const int rp = rowStart + m;
        int grow;
        if (GATE) {
            if (rp >= rowEnd) continue;
            grow = g_perm[rp];
        } else {
            grow = rp;
        }
        float* orow = Out + (size_t)grow * Nout + cb;
#pragma unroll
        for (int j = 0; j < 8; j++) {
            const int n = (j < 4) ? (tx * 4 + j) : (64 + tx * 4 + (j - 4));
            float v = acc[i][j];
            if (bp) v += bp[cb + n];
            if (do_relu) v = fmaxf(v, 0.f);
            v *= scale;
            if (do_accum) orow[n] += v;
            else          orow[n] = v;
        }
    }
}

// ---------------------------------------------------------------------------
// Launch: sort -> L1 shared (store relu) -> L1 gate (+= 0.9*relu, gathered)
//         -> L2 (store relu) -> L3 (plain store to d_out)
// ---------------------------------------------------------------------------
extern "C" void kernel_launch(void* const* d_in, const int* in_sizes, int n_in,
                              void* d_out, int out_size) {
    const float* x   = (const float*)d_in[0];
    const int*   gid = (const int*)  d_in[1];
    const float* W1  = (const float*)d_in[2];
    const float* b1  = (const float*)d_in[3];
    const float* W2  = (const float*)d_in[4];
    const float* b2  = (const float*)d_in[5];
    const float* W3  = (const float*)d_in[6];
    float* out = (float*)d_out;

    float *s_ptr = nullptr, *h2_ptr = nullptr;
    cudaGetSymbolAddress((void**)&s_ptr, g_s);
    cudaGetSymbolAddress((void**)&h2_ptr, g_h2);

    sort_gates<<<1, 256>>>(gid);

    dim3 blk(256);

    // Layer 1, shared block (block index G): s = relu(x @ W1_sh^T + b1_sh)
    sgemm<false><<<dim3(TWOD / BN, NROWS / BM), blk>>>(
        x, W1 + (size_t)NGATE * TWOD * INDIM, b1 + (size_t)NGATE * TWOD,
        s_ptr, TWOD, INDIM, /*relu=*/1, /*accum=*/0, 1.0f);

    // Layer 1, per-gate block: s[perm rows] += 0.9 * relu(x @ W1_g^T + b1_g)
    sgemm<true><<<dim3(TWOD / BN, NROWS / BM, NGATE), blk>>>(
        x, W1, b1, s_ptr, TWOD, INDIM, /*relu=*/1, /*accum=*/1, 0.9f);

    // Layer 2: h2 = relu(s @ W2^T + b2)
    sgemm<false><<<dim3(DDIM / BN, NROWS / BM), blk>>>(
        s_ptr, W2, b2, h2_ptr, DDIM, TWOD, /*relu=*/1, /*accum=*/0, 1.0f);

    // Layer 3: out = h2 @ W3^T
    sgemm<false><<<dim3(OUTDIM / BN, NROWS / BM), blk>>>(
        h2_ptr, W3, nullptr, out, OUTDIM, DDIM, /*relu=*/0, /*accum=*/0, 1.0f);
}

// round 2
// speedup vs baseline: 1.0024x; 1.0024x over previous
#include <cuda_runtime.h>
#include <cstdint>

#define NROWS 4096
#define INDIM 1024
#define DDIM  2048
#define TWOD  4096
#define NGATE 8
#define OUTDIM 1024

// Scratch (allocation-free rule: __device__ globals)
__device__ float g_s[(size_t)NROWS * TWOD];    // 64 MB: masked block-sum s
__device__ float g_h2[(size_t)NROWS * DDIM];   // 32 MB: relu(s @ W2^T + b2)
__device__ int   g_perm[NROWS];
__device__ int   g_off[NGATE + 1];

// ---------------------------------------------------------------------------
// Counting sort of rows by gate id (order within a gate is irrelevant to math)
// ---------------------------------------------------------------------------
__global__ void sort_gates(const int* __restrict__ gate_ids) {
    __shared__ int cnt[NGATE];
    __shared__ int base[NGATE];
    int t = threadIdx.x;
    if (t < NGATE) cnt[t] = 0;
    __syncthreads();
    for (int i = t; i < NROWS; i += blockDim.x)
        atomicAdd(&cnt[gate_ids[i]], 1);
    __syncthreads();
    if (t == 0) {
        int a = 0;
        for (int g = 0; g < NGATE; g++) { base[g] = a; g_off[g] = a; a += cnt[g]; }
        g_off[NGATE] = a;
    }
    __syncthreads();
    for (int i = t; i < NROWS; i += blockDim.x) {
        int g = gate_ids[i];
        int p = atomicAdd(&base[g], 1);
        g_perm[p] = i;
    }
}

// ---------------------------------------------------------------------------
// Register-blocked SGEMM: Out[m, n] (+)= epi( A[m, :] . W[n, :] + bias[n] )
// BM=BN=128, BK=16, 256 threads, 8x8 per thread (two 4x4 quads at +0 / +64).
// GATE=true: rows are gathered through g_perm within gate segment blockIdx.z;
//            weights/bias offset by gate block.
// ---------------------------------------------------------------------------
constexpr int BM = 128, BN = 128, BK = 16;

template<bool GATE>
__global__ __launch_bounds__(256)
void sgemm(const float* __restrict__ A,
           const float* __restrict__ W,
           const float* __restrict__ bias,
           float* __restrict__ Out,
           int Nout, int K,
           int do_relu, int do_accum, float scale)
{
    __shared__ float As[BK][BM];
    __shared__ float Bs[BK][BN];

    int rowStart, rowEnd;
    const float* Wp = W;
    const float* bp = bias;
    if (GATE) {
        int g = blockIdx.z;
        int s0 = g_off[g], s1 = g_off[g + 1];
        rowStart = s0 + blockIdx.y * BM;
        if (rowStart >= s1) return;
        rowEnd = s1;
        Wp = W + (size_t)g * Nout * K;
        if (bp) bp = bp + (size_t)g * Nout;
    } else {
        rowStart = blockIdx.y * BM;
        rowEnd = rowStart + BM;
    }
    const int cb = blockIdx.x * BN;
    const int tid = threadIdx.x;
    const int tx = tid & 15, ty = tid >> 4;

    // Two (m, k4) load slots per thread: e4 = tid + i*256, m = e4>>2, k4 = (e4&3)*4
    int rowg[2], mfrac[2], kfrac[2];
#pragma unroll
    for (int i = 0; i < 2; i++) {
        int e4 = tid + i * 256;
        mfrac[i] = e4 >> 2;
        kfrac[i] = (e4 & 3) << 2;
        int rp = rowStart + mfrac[i];
        if (GATE) rowg[i] = (rp < rowEnd) ? g_perm[rp] : -1;
        else      rowg[i] = rp;
    }

    float acc[8][8];
#pragma unroll
    for (int i = 0; i < 8; i++)
#pragma unroll
        for (int j = 0; j < 8; j++) acc[i][j] = 0.f;

    for (int k0 = 0; k0 < K; k0 += BK) {
#pragma unroll
        for (int i = 0; i < 2; i++) {
            const int m = mfrac[i], k4 = kfrac[i];
            float4 va = make_float4(0.f, 0.f, 0.f, 0.f);
            if (!GATE || rowg[i] >= 0)
                va = *reinterpret_cast<const float4*>(A + (size_t)rowg[i] * K + k0 + k4);
            As[k4 + 0][m] = va.x; As[k4 + 1][m] = va.y;
            As[k4 + 2][m] = va.z; As[k4 + 3][m] = va.w;
            float4 vb = *reinterpret_cast<const float4*>(Wp + (size_t)(cb + m) * K + k0 + k4);
            Bs[k4 + 0][m] = vb.x; Bs[k4 + 1][m] = vb.y;
            Bs[k4 + 2][m] = vb.z; Bs[k4 + 3][m] = vb.w;
        }
        __syncthreads();
#pragma unroll
        for (int kk = 0; kk < BK; kk++) {
            float4 a0 = *reinterpret_cast<const float4*>(&As[kk][ty * 4]);
            float4 a1 = *reinterpret_cast<const float4*>(&As[kk][64 + ty * 4]);
            float4 b0 = *reinterpret_cast<const float4*>(&Bs[kk][tx * 4]);
            float4 b1 = *reinterpret_cast<const float4*>(&Bs[kk][64 + tx * 4]);
            float a[8] = {a0.x, a0.y, a0.z, a0.w, a1.x, a1.y, a1.z, a1.w};
            float b[8] = {b0.x, b0.y, b0.z, b0.w, b1.x, b1.y, b1.z, b1.w};
#pragma unroll
            for (int i = 0; i < 8; i++)
#pragma unroll
                for (int j = 0; j < 8; j++)
                    acc[i][j] = fmaf(a[i], b[j], acc[i][j]);
        }
        __syncthreads();
    }

    // Epilogue
#pragma unroll
    for (int i = 0; i < 8; i++) {
        const int m = (i < 4) ? (ty * 4 + i) : (64 + ty * 4 + (i - 4));
        const int rp = rowStart + m;
        int grow;
        if (GATE) {
            if (rp >= rowEnd) continue;
            grow = g_perm[rp];
        } else {
            grow = rp;
        }
        float* orow = Out + (size_t)grow * Nout + cb;
#pragma unroll
        for (int j = 0; j < 8; j++) {
            const int n = (j < 4) ? (tx * 4 + j) : (64 + tx * 4 + (j - 4));
            float v = acc[i][j];
            if (bp) v += bp[cb + n];
            if (do_relu) v = fmaxf(v, 0.f);
            v *= scale;
            if (do_accum) orow[n] += v;
            else          orow[n] = v;
        }
    }
}

// ---------------------------------------------------------------------------
// Launch: sort -> L1 shared (store relu) -> L1 gate (+= 0.9*relu, gathered)
//         -> L2 (store relu) -> L3 (plain store to d_out)
// ---------------------------------------------------------------------------
extern "C" void kernel_launch(void* const* d_in, const int* in_sizes, int n_in,
                              void* d_out, int out_size) {
    const float* x   = (const float*)d_in[0];
    const int*   gid = (const int*)  d_in[1];
    const float* W1  = (const float*)d_in[2];
    const float* b1  = (const float*)d_in[3];
    const float* W2  = (const float*)d_in[4];
    const float* b2  = (const float*)d_in[5];
    const float* W3  = (const float*)d_in[6];
    float* out = (float*)d_out;

    float *s_ptr = nullptr, *h2_ptr = nullptr;
    cudaGetSymbolAddress((void**)&s_ptr, g_s);
    cudaGetSymbolAddress((void**)&h2_ptr, g_h2);

    sort_gates<<<1, 256>>>(gid);

    dim3 blk(256);

    // Layer 1, shared block (block index G): s = relu(x @ W1_sh^T + b1_sh)
    sgemm<false><<<dim3(TWOD / BN, NROWS / BM), blk>>>(
        x, W1 + (size_t)NGATE * TWOD * INDIM, b1 + (size_t)NGATE * TWOD,
        s_ptr, TWOD, INDIM, /*relu=*/1, /*accum=*/0, 1.0f);

    // Layer 1, per-gate block: s[perm rows] += 0.9 * relu(x @ W1_g^T + b1_g)
    sgemm<true><<<dim3(TWOD / BN, NROWS / BM, NGATE), blk>>>(
        x, W1, b1, s_ptr, TWOD, INDIM, /*relu=*/1, /*accum=*/1, 0.9f);

    // Layer 2: h2 = relu(s @ W2^T + b2)
    sgemm<false><<<dim3(DDIM / BN, NROWS / BM), blk>>>(
        s_ptr, W2, b2, h2_ptr, DDIM, TWOD, /*relu=*/1, /*accum=*/0, 1.0f);

    // Layer 3: out = h2 @ W3^T
    sgemm<false><<<dim3(OUTDIM / BN, NROWS / BM), blk>>>(
        h2_ptr, W3, nullptr, out, OUTDIM, DDIM, /*relu=*/0, /*accum=*/0, 1.0f);
}

// round 4
// speedup vs baseline: 2.2912x; 2.2858x over previous
#include <cuda_runtime.h>
#include <cuda_bf16.h>
#include <cstdint>

#define NROWS 4096
#define INDIM 1024
#define DDIM  2048
#define TWOD  4096
#define NGATE 8
#define OUTDIM 1024
#define W1R   (2*(1+NGATE)*DDIM)   // 36864

// ---------------------------------------------------------------------------
// Device scratch (allocation-free rule: __device__ globals)
// ---------------------------------------------------------------------------
__device__ __nv_bfloat16 g_xh [(size_t)NROWS * INDIM];
__device__ __nv_bfloat16 g_xl [(size_t)NROWS * INDIM];
__device__ __nv_bfloat16 g_W1h[(size_t)W1R   * INDIM];
__device__ __nv_bfloat16 g_W1l[(size_t)W1R   * INDIM];
__device__ __nv_bfloat16 g_W2h[(size_t)DDIM  * TWOD];
__device__ __nv_bfloat16 g_W2l[(size_t)DDIM  * TWOD];
__device__ __nv_bfloat16 g_W3h[(size_t)OUTDIM* DDIM];
__device__ __nv_bfloat16 g_W3l[(size_t)OUTDIM* DDIM];
__device__ __nv_bfloat16 g_sh [(size_t)NROWS * TWOD];
__device__ __nv_bfloat16 g_sl [(size_t)NROWS * TWOD];
__device__ __nv_bfloat16 g_h2h[(size_t)NROWS * DDIM];
__device__ __nv_bfloat16 g_h2l[(size_t)NROWS * DDIM];
__device__ int g_perm[NROWS];
__device__ int g_off[NGATE + 1];

// ---------------------------------------------------------------------------
// Counting sort of rows by gate id
// ---------------------------------------------------------------------------
__global__ void sort_gates(const int* __restrict__ gate_ids) {
    __shared__ int cnt[NGATE];
    __shared__ int base[NGATE];
    int t = threadIdx.x;
    if (t < NGATE) cnt[t] = 0;
    __syncthreads();
    for (int i = t; i < NROWS; i += blockDim.x)
        atomicAdd(&cnt[gate_ids[i]], 1);
    __syncthreads();
    if (t == 0) {
        int a = 0;
        for (int g = 0; g < NGATE; g++) { base[g] = a; g_off[g] = a; a += cnt[g]; }
        g_off[NGATE] = a;
    }
    __syncthreads();
    for (int i = t; i < NROWS; i += blockDim.x) {
        int g = gate_ids[i];
        int p = atomicAdd(&base[g], 1);
        g_perm[p] = i;
    }
}

// ---------------------------------------------------------------------------
// fp32 -> (bf16 hi, bf16 lo) split
// ---------------------------------------------------------------------------
__global__ __launch_bounds__(256) void split_f32(
    const float* __restrict__ in,
    __nv_bfloat16* __restrict__ hi, __nv_bfloat16* __restrict__ lo, int n4)
{
    int i = blockIdx.x * 256 + threadIdx.x;
    if (i >= n4) return;
    float4 v = reinterpret_cast<const float4*>(in)[i];
    __nv_bfloat16 h0 = __float2bfloat16(v.x);
    __nv_bfloat16 h1 = __float2bfloat16(v.y);
    __nv_bfloat16 h2 = __float2bfloat16(v.z);
    __nv_bfloat16 h3 = __float2bfloat16(v.w);
    __nv_bfloat16 l0 = __float2bfloat16(v.x - __bfloat162float(h0));
    __nv_bfloat16 l1 = __float2bfloat16(v.y - __bfloat162float(h1));
    __nv_bfloat16 l2 = __float2bfloat16(v.z - __bfloat162float(h2));
    __nv_bfloat16 l3 = __float2bfloat16(v.w - __bfloat162float(h3));
    reinterpret_cast<ushort4*>(hi)[i] = make_ushort4(
        __bfloat16_as_ushort(h0), __bfloat16_as_ushort(h1),
        __bfloat16_as_ushort(h2), __bfloat16_as_ushort(h3));
    reinterpret_cast<ushort4*>(lo)[i] = make_ushort4(
        __bfloat16_as_ushort(l0), __bfloat16_as_ushort(l1),
        __bfloat16_as_ushort(l2), __bfloat16_as_ushort(l3));
}

// ---------------------------------------------------------------------------
// Helpers (all portable to base sm_103 target: mma.sync + cp.async only)
// ---------------------------------------------------------------------------
__device__ __forceinline__ uint32_t smem_u32(const void* p) {
    uint32_t a;
    asm("{ .reg .u64 t; cvta.to.shared.u64 t, %1; cvt.u32.u64 %0, t; }"
        : "=r"(a) : "l"(p));
    return a;
}
__device__ __forceinline__ void cp16(uint32_t dst, const void* src, bool pred) {
    int sz = pred ? 16 : 0;
    asm volatile("cp.async.cg.shared.global [%0], [%1], 16, %2;"
                 :: "r"(dst), "l"(src), "r"(sz) : "memory");
}
__device__ __forceinline__ void mma16816(float* c, const uint32_t* a,
                                         const uint32_t* b) {
    asm volatile(
        "mma.sync.aligned.m16n8k16.row.col.f32.bf16.bf16.f32 "
        "{%0,%1,%2,%3}, {%4,%5,%6,%7}, {%8,%9}, {%0,%1,%2,%3};"
        : "+f"(c[0]), "+f"(c[1]), "+f"(c[2]), "+f"(c[3])
        : "r"(a[0]), "r"(a[1]), "r"(a[2]), "r"(a[3]), "r"(b[0]), "r"(b[1]));
}

constexpr int BM = 128, BN = 128, BK = 32;
constexpr int ROWB  = BK * 2;            // 64 bytes per smem row
constexpr int ARR   = BM * ROWB;         // 8KB per array (Ah/Al/Bh/Bl)
constexpr int STAGE = 4 * ARR;           // 32KB
constexpr int NST   = 3;
constexpr int SMEM_TOTAL = NST * STAGE;  // 96KB

// swizzle: 16B slot XOR'd by (row & 3); col < 64 so row bits untouched
__device__ __forceinline__ uint32_t swz(uint32_t x) {
    return x ^ (((x >> 6) & 3u) << 4);
}

// ---------------------------------------------------------------------------
// bf16x3 GEMM on mma.sync: Out[m,n] = epi( (Ah+Al)[m,:] . (Wh+Wl)[n,:] + bias )
// Epilogue: +bias, relu, *scale, += (addH+addL), store fp32 OR bf16 hi/lo split.
// GATE: rows gathered/scattered via g_perm segment blockIdx.z, W offset by gate.
// ---------------------------------------------------------------------------
template<bool GATE>
__global__ __launch_bounds__(256, 2)
void mma_gemm(const __nv_bfloat16* __restrict__ Ah,
              const __nv_bfloat16* __restrict__ Al,
              const __nv_bfloat16* __restrict__ Wh_,
              const __nv_bfloat16* __restrict__ Wl_,
              const float* __restrict__ bias_,
              float* __restrict__ outF,
              __nv_bfloat16* __restrict__ outH, __nv_bfloat16* __restrict__ outL,
              const __nv_bfloat16* __restrict__ addH,
              const __nv_bfloat16* __restrict__ addL,
              int Nout, int K, int do_relu, float scale)
{
    extern __shared__ char smem[];
    const uint32_t sb = smem_u32(smem);
    const int tid = threadIdx.x, wid = tid >> 5, lid = tid & 31;

    int rowStart, rowValid;
    const __nv_bfloat16* Wh = Wh_;
    const __nv_bfloat16* Wl = Wl_;
    const float* bp = bias_;
    if (GATE) {
        int g = blockIdx.z;
        int s0 = g_off[g], s1 = g_off[g + 1];
        rowStart = s0 + blockIdx.y * BM;
        if (rowStart >= s1) return;
        rowValid = min(BM, s1 - rowStart);
        size_t off = (size_t)g * Nout * K;
        Wh += off; Wl += off;
        if (bp) bp += (size_t)g * Nout;
    } else {
        rowStart = blockIdx.y * BM;
        rowValid = BM;
    }
    const int cb = blockIdx.x * BN;

    // ---- cp.async mapping: cid = tid + i*256 -> row = cid>>2, 16B chunk cid&3
    const __nv_bfloat16* pAh[2];
    const __nv_bfloat16* pAl[2];
    const __nv_bfloat16* pBh[2];
    const __nv_bfloat16* pBl[2];
    bool vA[2];
    uint32_t dOf[2];
#pragma unroll
    for (int i = 0; i < 2; i++) {
        int cid = tid + i * 256;
        int r = cid >> 2, c16 = cid & 3;
        dOf[i] = swz(r * ROWB + c16 * 16) + c16 * 0;
        int ar;
        if (GATE) { ar = (r < rowValid) ? g_perm[rowStart + r] : -1; }
        else      { ar = rowStart + r; }
        vA[i] = ar >= 0;
        size_t aoff = vA[i] ? (size_t)ar * K : 0;
        pAh[i] = Ah + aoff;
        pAl[i] = Al + aoff;
        pBh[i] = Wh + (size_t)(cb + r) * K;
        pBl[i] = Wl + (size_t)(cb + r) * K;
        // src 16B offset within row handled at load time: + c16*8 elements
        pAh[i] += c16 * 8; pAl[i] += c16 * 8; pBh[i] += c16 * 8; pBl[i] += c16 * 8;
    }

    const int T = K / BK;
    auto load_tile = [&](int kt) {
        uint32_t st = sb + (kt % NST) * STAGE;
        int ke = kt * BK;
#pragma unroll
        for (int i = 0; i < 2; i++) {
            cp16(st + 0 * ARR + dOf[i], pAh[i] + ke, vA[i]);
            cp16(st + 1 * ARR + dOf[i], pAl[i] + ke, vA[i]);
            cp16(st + 2 * ARR + dOf[i], pBh[i] + ke, true);
            cp16(st + 3 * ARR + dOf[i], pBl[i] + ke, true);
        }
        asm volatile("cp.async.commit_group;" ::: "memory");
    };

    float acc[4][4][4];
#pragma unroll
    for (int a = 0; a < 4; a++)
#pragma unroll
        for (int b = 0; b < 4; b++)
#pragma unroll
            for (int c = 0; c < 4; c++) acc[a][b][c] = 0.f;

    const int gr  = lid >> 2;            // 0..7
    const int lc4 = (lid & 3) * 4;       // byte offset of k-pair
    const int wm  = (wid >> 2) * 64;     // warp M origin (0 / 64)
    const int wn  = (wid & 3) * 32;      // warp N origin
    const uint32_t xm = (uint32_t)(gr & 3) << 4;  // swizzle mask (row&3 == gr&3)

    load_tile(0);
    load_tile(1);

    for (int kt = 0; kt < T; kt++) {
        if (kt < T - 1) asm volatile("cp.async.wait_group 1;" ::: "memory");
        else            asm volatile("cp.async.wait_group 0;" ::: "memory");
        __syncthreads();
        if (kt + 2 < T) load_tile(kt + 2);

        const char* S = smem + (kt % NST) * STAGE;
#pragma unroll
        for (int kh = 0; kh < 2; kh++) {
            const uint32_t cA = (uint32_t)((lc4 + kh * 32));
            uint32_t ah[4][4], al[4][4];
#pragma unroll
            for (int mt = 0; mt < 4; mt++) {
                const int r0 = wm + mt * 16 + gr;
#pragma unroll
                for (int j = 0; j < 4; j++) {
                    uint32_t off = (uint32_t)(r0 + (j & 1) * 8) * ROWB
                                 + (((cA + (j >> 1) * 16)) ^ xm);
                    ah[mt][j] = *(const uint32_t*)(S + 0 * ARR + off);
                    al[mt][j] = *(const uint32_t*)(S + 1 * ARR + off);
                }
            }
#pragma unroll
            for (int nt = 0; nt < 4; nt++) {
                const int n0 = wn + nt * 8 + gr;
                uint32_t bh[2], bl[2];
#pragma unroll
                for (int j = 0; j < 2; j++) {
                    uint32_t off = (uint32_t)n0 * ROWB + ((cA + j * 16) ^ xm);
                    bh[j] = *(const uint32_t*)(S + 2 * ARR + off);
                    bl[j] = *(const uint32_t*)(S + 3 * ARR + off);
                }
#pragma unroll
                for (int mt = 0; mt < 4; mt++) {
                    mma16816(acc[mt][nt], ah[mt], bh);
                    mma16816(acc[mt][nt], ah[mt], bl);
                    mma16816(acc[mt][nt], al[mt], bh);
                }
            }
        }
    }

    // ------------------------------- epilogue ------------------------------
#pragma unroll
    for (int mt = 0; mt < 4; mt++) {
#pragma unroll
        for (int half = 0; half < 2; half++) {
            const int rloc = wm + mt * 16 + gr + half * 8;
            int grow;
            bool valid = true;
            if (GATE) {
                valid = (rloc < rowValid);
                grow = valid ? g_perm[rowStart + rloc] : 0;
            } else {
                grow = rowStart + rloc;
            }
            if (!valid) continue;
#pragma unroll
            for (int nt = 0; nt < 4; nt++) {
                const int col = cb + wn + nt * 8 + (lid & 3) * 2;
                float v0 = acc[mt][nt][half * 2 + 0];
                float v1 = acc[mt][nt][half * 2 + 1];
                if (bp) {
                    float2 bb = *(const float2*)(bp + col);
                    v0 += bb.x; v1 += bb.y;
                }
                if (do_relu) { v0 = fmaxf(v0, 0.f); v1 = fmaxf(v1, 0.f); }
                v0 *= scale; v1 *= scale;
                const size_t rb = (size_t)grow * Nout + col;
                if (addH) {
                    uint32_t uh = *(const uint32_t*)(addH + rb);
                    uint32_t ul = *(const uint32_t*)(addL + rb);
                    float2 fh = __bfloat1622float2(
                        *reinterpret_cast<__nv_bfloat162*>(&uh));
                    float2 fl = __bfloat1622float2(
                        *reinterpret_cast<__nv_bfloat162*>(&ul));
                    v0 += fh.x + fl.x; v1 += fh.y + fl.y;
                }
                if (outF) {
                    *(float2*)(outF + rb) = make_float2(v0, v1);
                } else {
                    __nv_bfloat16 h0 = __float2bfloat16(v0);
                    __nv_bfloat16 h1 = __float2bfloat16(v1);
                    __nv_bfloat16 l0 = __float2bfloat16(v0 - __bfloat162float(h0));
                    __nv_bfloat16 l1 = __float2bfloat16(v1 - __bfloat162float(h1));
                    uint32_t ph = (uint32_t)__bfloat16_as_ushort(h0) |
                                  ((uint32_t)__bfloat16_as_ushort(h1) << 16);
                    uint32_t pl = (uint32_t)__bfloat16_as_ushort(l0) |
                                  ((uint32_t)__bfloat16_as_ushort(l1) << 16);
                    *(uint32_t*)(outH + rb) = ph;
                    *(uint32_t*)(outL + rb) = pl;
                }
            }
        }
    }
}

// ---------------------------------------------------------------------------
extern "C" void kernel_launch(void* const* d_in, const int* in_sizes, int n_in,
                              void* d_out, int out_size) {
    const float* x   = (const float*)d_in[0];
    const int*   gid = (const int*)  d_in[1];
    const float* W1  = (const float*)d_in[2];
    const float* b1  = (const float*)d_in[3];
    const float* W2  = (const float*)d_in[4];
    const float* b2  = (const float*)d_in[5];
    const float* W3  = (const float*)d_in[6];
    float* out = (float*)d_out;

    __nv_bfloat16 *xh, *xl, *w1h, *w1l, *w2h, *w2l, *w3h, *w3l, *sh, *sl, *h2h, *h2l;
    cudaGetSymbolAddress((void**)&xh,  g_xh);  cudaGetSymbolAddress((void**)&xl,  g_xl);
    cudaGetSymbolAddress((void**)&w1h, g_W1h); cudaGetSymbolAddress((void**)&w1l, g_W1l);
    cudaGetSymbolAddress((void**)&w2h, g_W2h); cudaGetSymbolAddress((void**)&w2l, g_W2l);
    cudaGetSymbolAddress((void**)&w3h, g_W3h); cudaGetSymbolAddress((void**)&w3l, g_W3l);
    cudaGetSymbolAddress((void**)&sh,  g_sh);  cudaGetSymbolAddress((void**)&sl,  g_sl);
    cudaGetSymbolAddress((void**)&h2h, g_h2h); cudaGetSymbolAddress((void**)&h2l, g_h2l);

    cudaFuncSetAttribute((const void*)mma_gemm<true>,
                         cudaFuncAttributeMaxDynamicSharedMemorySize, SMEM_TOTAL);
    cudaFuncSetAttribute((const void*)mma_gemm<false>,
                         cudaFuncAttributeMaxDynamicSharedMemorySize, SMEM_TOTAL);

    sort_gates<<<1, 256>>>(gid);

    auto nblk = [](size_t elems) { return (int)((elems / 4 + 255) / 256); };
    split_f32<<<nblk((size_t)NROWS * INDIM), 256>>>(x,  xh,  xl,  NROWS * INDIM / 4);
    split_f32<<<nblk((size_t)W1R * INDIM),   256>>>(W1, w1h, w1l, (int)((size_t)W1R * INDIM / 4));
    split_f32<<<nblk((size_t)DDIM * TWOD),   256>>>(W2, w2h, w2l, DDIM * TWOD / 4);
    split_f32<<<nblk((size_t)OUTDIM * DDIM), 256>>>(W3, w3h, w3l, OUTDIM * DDIM / 4);

    // L1 gate blocks: s = 0.9*relu(x @ W1_g^T + b1_g), rows scattered via perm
    mma_gemm<true><<<dim3(TWOD / BN, NROWS / BM, NGATE), 256, SMEM_TOTAL>>>(
        xh, xl, w1h, w1l, b1,
        nullptr, sh, sl, nullptr, nullptr,
        TWOD, INDIM, /*relu=*/1, /*scale=*/0.9f);

    // L1 shared block: s += relu(x @ W1_sh^T + b1_sh)  (adds prior s, re-splits)
    mma_gemm<false><<<dim3(TWOD / BN, NROWS / BM), 256, SMEM_TOTAL>>>(
        xh, xl,
        w1h + (size_t)NGATE * TWOD * INDIM, w1l + (size_t)NGATE * TWOD * INDIM,
        b1 + (size_t)NGATE * TWOD,
        nullptr, sh, sl, sh, sl,
        TWOD, INDIM, /*relu=*/1, /*scale=*/1.0f);

    // L2: h2 = relu(s @ W2^T + b2)
    mma_gemm<false><<<dim3(DDIM / BN, NROWS / BM), 256, SMEM_TOTAL>>>(
        sh, sl, w2h, w2l, b2,
        nullptr, h2h, h2l, nullptr, nullptr,
        DDIM, TWOD, /*relu=*/1, /*scale=*/1.0f);

    // L3: out = h2 @ W3^T  (fp32 store)
    mma_gemm<false><<<dim3(OUTDIM / BN, NROWS / BM), 256, SMEM_TOTAL>>>(
        h2h, h2l, w3h, w3l, nullptr,
        out, nullptr, nullptr, nullptr, nullptr,
        OUTDIM, DDIM, /*relu=*/0, /*scale=*/1.0f);
}

// round 6
// speedup vs baseline: 2.8063x; 1.2248x over previous
#include <cuda_runtime.h>
#include <cuda_bf16.h>
#include <cstdint>

#define NROWS 4096
#define INDIM 1024
#define DDIM  2048
#define TWOD  4096
#define NGATE 8
#define OUTDIM 1024
#define W1R   (2*(1+NGATE)*DDIM)   // 36864

// ---------------------------------------------------------------------------
// Device scratch (allocation-free rule: __device__ globals)
// ---------------------------------------------------------------------------
__device__ __nv_bfloat16 g_xh [(size_t)NROWS * INDIM];
__device__ __nv_bfloat16 g_xl [(size_t)NROWS * INDIM];
__device__ __nv_bfloat16 g_W1h[(size_t)W1R   * INDIM];
__device__ __nv_bfloat16 g_W1l[(size_t)W1R   * INDIM];
__device__ __nv_bfloat16 g_W2h[(size_t)DDIM  * TWOD];
__device__ __nv_bfloat16 g_W2l[(size_t)DDIM  * TWOD];
__device__ __nv_bfloat16 g_W3h[(size_t)OUTDIM* DDIM];
__device__ __nv_bfloat16 g_W3l[(size_t)OUTDIM* DDIM];
__device__ __nv_bfloat16 g_sh [(size_t)NROWS * TWOD];
__device__ __nv_bfloat16 g_sl [(size_t)NROWS * TWOD];
__device__ __nv_bfloat16 g_h2h[(size_t)NROWS * DDIM];
__device__ __nv_bfloat16 g_h2l[(size_t)NROWS * DDIM];
__device__ int g_perm[NROWS];
__device__ int g_off[NGATE + 1];

// ---------------------------------------------------------------------------
__global__ void sort_gates(const int* __restrict__ gate_ids) {
    __shared__ int cnt[NGATE];
    __shared__ int base[NGATE];
    int t = threadIdx.x;
    if (t < NGATE) cnt[t] = 0;
    __syncthreads();
    for (int i = t; i < NROWS; i += blockDim.x)
        atomicAdd(&cnt[gate_ids[i]], 1);
    __syncthreads();
    if (t == 0) {
        int a = 0;
        for (int g = 0; g < NGATE; g++) { base[g] = a; g_off[g] = a; a += cnt[g]; }
        g_off[NGATE] = a;
    }
    __syncthreads();
    for (int i = t; i < NROWS; i += blockDim.x) {
        int g = gate_ids[i];
        int p = atomicAdd(&base[g], 1);
        g_perm[p] = i;
    }
}

// ---------------------------------------------------------------------------
__global__ __launch_bounds__(256) void split_f32(
    const float* __restrict__ in,
    __nv_bfloat16* __restrict__ hi, __nv_bfloat16* __restrict__ lo, int n4)
{
    int i = blockIdx.x * 256 + threadIdx.x;
    if (i >= n4) return;
    float4 v = reinterpret_cast<const float4*>(in)[i];
    __nv_bfloat16 h0 = __float2bfloat16(v.x);
    __nv_bfloat16 h1 = __float2bfloat16(v.y);
    __nv_bfloat16 h2 = __float2bfloat16(v.z);
    __nv_bfloat16 h3 = __float2bfloat16(v.w);
    __nv_bfloat16 l0 = __float2bfloat16(v.x - __bfloat162float(h0));
    __nv_bfloat16 l1 = __float2bfloat16(v.y - __bfloat162float(h1));
    __nv_bfloat16 l2 = __float2bfloat16(v.z - __bfloat162float(h2));
    __nv_bfloat16 l3 = __float2bfloat16(v.w - __bfloat162float(h3));
    reinterpret_cast<ushort4*>(hi)[i] = make_ushort4(
        __bfloat16_as_ushort(h0), __bfloat16_as_ushort(h1),
        __bfloat16_as_ushort(h2), __bfloat16_as_ushort(h3));
    reinterpret_cast<ushort4*>(lo)[i] = make_ushort4(
        __bfloat16_as_ushort(l0), __bfloat16_as_ushort(l1),
        __bfloat16_as_ushort(l2), __bfloat16_as_ushort(l3));
}

// ---------------------------------------------------------------------------
// Helpers (portable to base sm_103: mma.sync + cp.async + ldmatrix)
// ---------------------------------------------------------------------------
__device__ __forceinline__ uint32_t smem_u32(const void* p) {
    uint32_t a;
    asm("{ .reg .u64 t; cvta.to.shared.u64 t, %1; cvt.u32.u64 %0, t; }"
        : "=r"(a) : "l"(p));
    return a;
}
__device__ __forceinline__ void cp16(uint32_t dst, const void* src, bool pred) {
    int sz = pred ? 16 : 0;
    asm volatile("cp.async.cg.shared.global [%0], [%1], 16, %2;"
                 :: "r"(dst), "l"(src), "r"(sz) : "memory");
}
__device__ __forceinline__ void mma16816(float* c, const uint32_t* a,
                                         const uint32_t* b) {
    asm volatile(
        "mma.sync.aligned.m16n8k16.row.col.f32.bf16.bf16.f32 "
        "{%0,%1,%2,%3}, {%4,%5,%6,%7}, {%8,%9}, {%0,%1,%2,%3};"
        : "+f"(c[0]), "+f"(c[1]), "+f"(c[2]), "+f"(c[3])
        : "r"(a[0]), "r"(a[1]), "r"(a[2]), "r"(a[3]), "r"(b[0]), "r"(b[1]));
}
__device__ __forceinline__ void ldsm4(uint32_t* r, uint32_t addr) {
    asm volatile("ldmatrix.sync.aligned.m8n8.x4.shared.b16 {%0,%1,%2,%3}, [%4];"
                 : "=r"(r[0]), "=r"(r[1]), "=r"(r[2]), "=r"(r[3]) : "r"(addr));
}

constexpr int BM = 128, BN = 128, BK = 32;
constexpr int ROWB  = BK * 2;            // 64 bytes per smem row
constexpr int ARR   = BM * ROWB;         // 8KB per array (Ah/Al/Bh/Bl)
constexpr int STAGE = 4 * ARR;           // 32KB
constexpr int NST   = 3;
constexpr int SMEM_TOTAL = NST * STAGE;  // 96KB
constexpr int THREADS = 128;             // 4 warps, 2x2, 64x64 warp tiles

// swizzle: 16B slot XOR'd by (row>>1)&3 — conflict-free for ldmatrix 8-row
// groups. IMPORTANT: XOR must be applied to the FINAL column (incl. K-half
// offset); adding after the XOR can carry into the row bits (round-5 OOB bug).
__device__ __forceinline__ uint32_t swz_off(uint32_t row, uint32_t col) {
    return row * ROWB + (col ^ (((row >> 1) & 3u) << 4));
}

// ---------------------------------------------------------------------------
// bf16x3 GEMM on mma.sync + ldmatrix:
//   Out[m,n] = epi( (Ah+Al)[m,:].(Wh+Wl)[n,:] + bias )
// Epilogue: +bias, relu, *scale, += (addH+addL), fp32 store OR bf16 hi/lo split.
// GATE: rows gathered/scattered via g_perm segment blockIdx.z, W offset by gate.
// ---------------------------------------------------------------------------
template<bool GATE>
__global__ __launch_bounds__(THREADS, 2)
void mma_gemm(const __nv_bfloat16* __restrict__ Ah,
              const __nv_bfloat16* __restrict__ Al,
              const __nv_bfloat16* __restrict__ Wh_,
              const __nv_bfloat16* __restrict__ Wl_,
              const float* __restrict__ bias_,
              float* __restrict__ outF,
              __nv_bfloat16* __restrict__ outH, __nv_bfloat16* __restrict__ outL,
              const __nv_bfloat16* __restrict__ addH,
              const __nv_bfloat16* __restrict__ addL,
              int Nout, int K, int do_relu, float scale)
{
    extern __shared__ char smem[];
    const uint32_t sb = smem_u32(smem);
    const int tid = threadIdx.x, wid = tid >> 5, lid = tid & 31;

    int rowStart, rowValid;
    const __nv_bfloat16* Wh = Wh_;
    const __nv_bfloat16* Wl = Wl_;
    const float* bp = bias_;
    if (GATE) {
        int g = blockIdx.z;
        int s0 = g_off[g], s1 = g_off[g + 1];
        rowStart = s0 + blockIdx.y * BM;
        if (rowStart >= s1) return;
        rowValid = min(BM, s1 - rowStart);
        size_t off = (size_t)g * Nout * K;
        Wh += off; Wl += off;
        if (bp) bp += (size_t)g * Nout;
    } else {
        rowStart = blockIdx.y * BM;
        rowValid = BM;
    }
    const int cb = blockIdx.x * BN;

    // ---- cp.async mapping: 128 threads x 4 iters cover 512 chunks per array
    const __nv_bfloat16* pAh[4];
    const __nv_bfloat16* pAl[4];
    const __nv_bfloat16* pBh[4];
    const __nv_bfloat16* pBl[4];
    bool vA[4];
    uint32_t dOf[4];
#pragma unroll
    for (int i = 0; i < 4; i++) {
        int cid = tid + i * THREADS;
        int r = cid >> 2, c16 = cid & 3;
        dOf[i] = swz_off(r, c16 * 16);
        int ar;
        if (GATE) { ar = (r < rowValid) ? g_perm[rowStart + r] : -1; }
        else      { ar = rowStart + r; }
        vA[i] = ar >= 0;
        size_t aoff = (vA[i] ? (size_t)ar * K : 0) + c16 * 8;
        pAh[i] = Ah + aoff;
        pAl[i] = Al + aoff;
        size_t boff = (size_t)(cb + r) * K + c16 * 8;
        pBh[i] = Wh + boff;
        pBl[i] = Wl + boff;
    }

    const int T = K / BK;
    auto load_tile = [&](int kt) {
        uint32_t st = sb + (kt % NST) * STAGE;
        int ke = kt * BK;
#pragma unroll
        for (int i = 0; i < 4; i++) {
            cp16(st + 0 * ARR + dOf[i], pAh[i] + ke, vA[i]);
            cp16(st + 1 * ARR + dOf[i], pAl[i] + ke, vA[i]);
            cp16(st + 2 * ARR + dOf[i], pBh[i] + ke, true);
            cp16(st + 3 * ARR + dOf[i], pBl[i] + ke, true);
        }
        asm volatile("cp.async.commit_group;" ::: "memory");
    };

    float acc[4][8][4];
#pragma unroll
    for (int a = 0; a < 4; a++)
#pragma unroll
        for (int b = 0; b < 8; b++)
#pragma unroll
            for (int c = 0; c < 4; c++) acc[a][b][c] = 0.f;

    // warp tiling: 2x2 warps, 64x64 per warp
    const int wm = (wid >> 1) * 64;
    const int wn = (wid & 1) * 64;
    const int lg = lid >> 3, l7 = lid & 7;

    // ldmatrix lane components: row offset + mask kept separate from column so
    // the K-half offset is added BEFORE the swizzle XOR (no carry into row).
    uint32_t rowA[4], mskA[4], rowB[4], mskB[4];
    const uint32_t colA = (uint32_t)(lg >> 1) << 4;
    const uint32_t colB = (uint32_t)(lg & 1) << 4;
#pragma unroll
    for (int mt = 0; mt < 4; mt++) {
        uint32_t row = wm + mt * 16 + ((lg & 1) << 3) + l7;
        rowA[mt] = row * ROWB;
        mskA[mt] = ((row >> 1) & 3u) << 4;
    }
#pragma unroll
    for (int np = 0; np < 4; np++) {
        uint32_t row = wn + np * 16 + ((lg >> 1) << 3) + l7;
        rowB[np] = row * ROWB;
        mskB[np] = ((row >> 1) & 3u) << 4;
    }

    load_tile(0);
    load_tile(1);

    for (int kt = 0; kt < T; kt++) {
        if (kt < T - 1) asm volatile("cp.async.wait_group 1;" ::: "memory");
        else            asm volatile("cp.async.wait_group 0;" ::: "memory");
        __syncthreads();
        if (kt + 2 < T) load_tile(kt + 2);

        const uint32_t S = sb + (kt % NST) * STAGE;
#pragma unroll
        for (int kh = 0; kh < 2; kh++) {
            const uint32_t kof = kh * 32;
            uint32_t ah[4][4], al[4][4], bh[4][4], bl[4][4];
#pragma unroll
            for (int mt = 0; mt < 4; mt++) {
                uint32_t off = rowA[mt] + ((colA + kof) ^ mskA[mt]);
                ldsm4(ah[mt], S + 0 * ARR + off);
                ldsm4(al[mt], S + 1 * ARR + off);
            }
#pragma unroll
            for (int np = 0; np < 4; np++) {
                uint32_t off = rowB[np] + ((colB + kof) ^ mskB[np]);
                ldsm4(bh[np], S + 2 * ARR + off);
                ldsm4(bl[np], S + 3 * ARR + off);
            }
#pragma unroll
            for (int mt = 0; mt < 4; mt++) {
#pragma unroll
                for (int np = 0; np < 4; np++) {
                    // np covers nt = 2np (regs 0,1) and nt = 2np+1 (regs 2,3)
                    mma16816(acc[mt][2 * np],     ah[mt], &bh[np][0]);
                    mma16816(acc[mt][2 * np],     ah[mt], &bl[np][0]);
                    mma16816(acc[mt][2 * np],     al[mt], &bh[np][0]);
                    mma16816(acc[mt][2 * np + 1], ah[mt], &bh[np][2]);
                    mma16816(acc[mt][2 * np + 1], ah[mt], &bl[np][2]);
                    mma16816(acc[mt][2 * np + 1], al[mt], &bh[np][2]);
                }
            }
        }
    }

    // ------------------------------- epilogue ------------------------------
    const int gr = lid >> 2;
#pragma unroll
    for (int mt = 0; mt < 4; mt++) {
#pragma unroll
        for (int half = 0; half < 2; half++) {
            const int rloc = wm + mt * 16 + gr + half * 8;
            int grow;
            bool valid = true;
            if (GATE) {
                valid = (rloc < rowValid);
                grow = valid ? g_perm[rowStart + rloc] : 0;
            } else {
                grow = rowStart + rloc;
            }
            if (!valid) continue;
#pragma unroll
            for (int nt = 0; nt < 8; nt++) {
                const int col = cb + wn + nt * 8 + (lid & 3) * 2;
                float v0 = acc[mt][nt][half * 2 + 0];
                float v1 = acc[mt][nt][half * 2 + 1];
                if (bp) {
                    float2 bb = *(const float2*)(bp + col);
                    v0 += bb.x; v1 += bb.y;
                }
                if (do_relu) { v0 = fmaxf(v0, 0.f); v1 = fmaxf(v1, 0.f); }
                v0 *= scale; v1 *= scale;
                const size_t rb = (size_t)grow * Nout + col;
                if (addH) {
                    uint32_t uh = *(const uint32_t*)(addH + rb);
                    uint32_t ul = *(const uint32_t*)(addL + rb);
                    float2 fh = __bfloat1622float2(
                        *reinterpret_cast<__nv_bfloat162*>(&uh));
                    float2 fl = __bfloat1622float2(
                        *reinterpret_cast<__nv_bfloat162*>(&ul));
                    v0 += fh.x + fl.x; v1 += fh.y + fl.y;
                }
                if (outF) {
                    *(float2*)(outF + rb) = make_float2(v0, v1);
                } else {
                    __nv_bfloat16 h0 = __float2bfloat16(v0);
                    __nv_bfloat16 h1 = __float2bfloat16(v1);
                    __nv_bfloat16 l0 = __float2bfloat16(v0 - __bfloat162float(h0));
                    __nv_bfloat16 l1 = __float2bfloat16(v1 - __bfloat162float(h1));
                    uint32_t ph = (uint32_t)__bfloat16_as_ushort(h0) |
                                  ((uint32_t)__bfloat16_as_ushort(h1) << 16);
                    uint32_t pl = (uint32_t)__bfloat16_as_ushort(l0) |
                                  ((uint32_t)__bfloat16_as_ushort(l1) << 16);
                    *(uint32_t*)(outH + rb) = ph;
                    *(uint32_t*)(outL + rb) = pl;
                }
            }
        }
    }
}

// ---------------------------------------------------------------------------
extern "C" void kernel_launch(void* const* d_in, const int* in_sizes, int n_in,
                              void* d_out, int out_size) {
    const float* x   = (const float*)d_in[0];
    const int*   gid = (const int*)  d_in[1];
    const float* W1  = (const float*)d_in[2];
    const float* b1  = (const float*)d_in[3];
    const float* W2  = (const float*)d_in[4];
    const float* b2  = (const float*)d_in[5];
    const float* W3  = (const float*)d_in[6];
    float* out = (float*)d_out;

    __nv_bfloat16 *xh, *xl, *w1h, *w1l, *w2h, *w2l, *w3h, *w3l, *sh, *sl, *h2h, *h2l;
    cudaGetSymbolAddress((void**)&xh,  g_xh);  cudaGetSymbolAddress((void**)&xl,  g_xl);
    cudaGetSymbolAddress((void**)&w1h, g_W1h); cudaGetSymbolAddress((void**)&w1l, g_W1l);
    cudaGetSymbolAddress((void**)&w2h, g_W2h); cudaGetSymbolAddress((void**)&w2l, g_W2l);
    cudaGetSymbolAddress((void**)&w3h, g_W3h); cudaGetSymbolAddress((void**)&w3l, g_W3l);
    cudaGetSymbolAddress((void**)&sh,  g_sh);  cudaGetSymbolAddress((void**)&sl,  g_sl);
    cudaGetSymbolAddress((void**)&h2h, g_h2h); cudaGetSymbolAddress((void**)&h2l, g_h2l);

    cudaFuncSetAttribute((const void*)mma_gemm<true>,
                         cudaFuncAttributeMaxDynamicSharedMemorySize, SMEM_TOTAL);
    cudaFuncSetAttribute((const void*)mma_gemm<false>,
                         cudaFuncAttributeMaxDynamicSharedMemorySize, SMEM_TOTAL);

    sort_gates<<<1, 256>>>(gid);

    auto nblk = [](size_t elems) { return (int)((elems / 4 + 255) / 256); };
    split_f32<<<nblk((size_t)NROWS * INDIM), 256>>>(x,  xh,  xl,  NROWS * INDIM / 4);
    split_f32<<<nblk((size_t)W1R * INDIM),   256>>>(W1, w1h, w1l, (int)((size_t)W1R * INDIM / 4));
    split_f32<<<nblk((size_t)DDIM * TWOD),   256>>>(W2, w2h, w2l, DDIM * TWOD / 4);
    split_f32<<<nblk((size_t)OUTDIM * DDIM), 256>>>(W3, w3h, w3l, OUTDIM * DDIM / 4);

    // L1 gate blocks: s = 0.9*relu(x @ W1_g^T + b1_g), rows scattered via perm
    mma_gemm<true><<<dim3(TWOD / BN, NROWS / BM, NGATE), THREADS, SMEM_TOTAL>>>(
        xh, xl, w1h, w1l, b1,
        nullptr, sh, sl, nullptr, nullptr,
        TWOD, INDIM, /*relu=*/1, /*scale=*/0.9f);

    // L1 shared block: s += relu(x @ W1_sh^T + b1_sh)  (adds prior s, re-splits)
    mma_gemm<false><<<dim3(TWOD / BN, NROWS / BM), THREADS, SMEM_TOTAL>>>(
        xh, xl,
        w1h + (size_t)NGATE * TWOD * INDIM, w1l + (size_t)NGATE * TWOD * INDIM,
        b1 + (size_t)NGATE * TWOD,
        nullptr, sh, sl, sh, sl,
        TWOD, INDIM, /*relu=*/1, /*scale=*/1.0f);

    // L2: h2 = relu(s @ W2^T + b2)
    mma_gemm<false><<<dim3(DDIM / BN, NROWS / BM), THREADS, SMEM_TOTAL>>>(
        sh, sl, w2h, w2l, b2,
        nullptr, h2h, h2l, nullptr, nullptr,
        DDIM, TWOD, /*relu=*/1, /*scale=*/1.0f);

    // L3: out = h2 @ W3^T  (fp32 store)
    mma_gemm<false><<<dim3(OUTDIM / BN, NROWS / BM), THREADS, SMEM_TOTAL>>>(
        h2h, h2l, w3h, w3l, nullptr,
        out, nullptr, nullptr, nullptr, nullptr,
        OUTDIM, DDIM, /*relu=*/0, /*scale=*/1.0f);
}

// round 7
// speedup vs baseline: 4.0374x; 1.4387x over previous
#include <cuda_runtime.h>
#include <cuda_fp16.h>
#include <cstdint>

#define NROWS 4096
#define INDIM 1024
#define DDIM  2048
#define TWOD  4096
#define NGATE 8
#define OUTDIM 1024
#define W1R   (2*(1+NGATE)*DDIM)   // 36864

// ---------------------------------------------------------------------------
// Device scratch (allocation-free rule: __device__ globals)
// A-side operands are split fp16 hi/lo; weights are single fp16.
// ---------------------------------------------------------------------------
__device__ __half g_xh [(size_t)NROWS * INDIM];
__device__ __half g_xl [(size_t)NROWS * INDIM];
__device__ __half g_W1f[(size_t)W1R   * INDIM];
__device__ __half g_W2f[(size_t)DDIM  * TWOD];
__device__ __half g_W3f[(size_t)OUTDIM* DDIM];
__device__ __half g_sh [(size_t)NROWS * TWOD];
__device__ __half g_sl [(size_t)NROWS * TWOD];
__device__ __half g_h2h[(size_t)NROWS * DDIM];
__device__ __half g_h2l[(size_t)NROWS * DDIM];
__device__ int g_perm[NROWS];
__device__ int g_off[NGATE + 1];

// ---------------------------------------------------------------------------
__global__ void sort_gates(const int* __restrict__ gate_ids) {
    __shared__ int cnt[NGATE];
    __shared__ int base[NGATE];
    int t = threadIdx.x;
    if (t < NGATE) cnt[t] = 0;
    __syncthreads();
    for (int i = t; i < NROWS; i += blockDim.x)
        atomicAdd(&cnt[gate_ids[i]], 1);
    __syncthreads();
    if (t == 0) {
        int a = 0;
        for (int g = 0; g < NGATE; g++) { base[g] = a; g_off[g] = a; a += cnt[g]; }
        g_off[NGATE] = a;
    }
    __syncthreads();
    for (int i = t; i < NROWS; i += blockDim.x) {
        int g = gate_ids[i];
        int p = atomicAdd(&base[g], 1);
        g_perm[p] = i;
    }
}

// ---------------------------------------------------------------------------
// fp32 -> (fp16 hi, fp16 lo) exact split (activations)
// ---------------------------------------------------------------------------
__global__ __launch_bounds__(256) void split_f32h(
    const float* __restrict__ in,
    __half* __restrict__ hi, __half* __restrict__ lo, int n4)
{
    int i = blockIdx.x * 256 + threadIdx.x;
    if (i >= n4) return;
    float4 v = reinterpret_cast<const float4*>(in)[i];
    __half h0 = __float2half_rn(v.x);
    __half h1 = __float2half_rn(v.y);
    __half h2 = __float2half_rn(v.z);
    __half h3 = __float2half_rn(v.w);
    __half l0 = __float2half_rn(v.x - __half2float(h0));
    __half l1 = __float2half_rn(v.y - __half2float(h1));
    __half l2 = __float2half_rn(v.z - __half2float(h2));
    __half l3 = __float2half_rn(v.w - __half2float(h3));
    reinterpret_cast<ushort4*>(hi)[i] = make_ushort4(
        __half_as_ushort(h0), __half_as_ushort(h1),
        __half_as_ushort(h2), __half_as_ushort(h3));
    reinterpret_cast<ushort4*>(lo)[i] = make_ushort4(
        __half_as_ushort(l0), __half_as_ushort(l1),
        __half_as_ushort(l2), __half_as_ushort(l3));
}

// fp32 -> fp16 (weights, single rounding)
__global__ __launch_bounds__(256) void conv_f32h(
    const float* __restrict__ in, __half* __restrict__ outp, int n4)
{
    int i = blockIdx.x * 256 + threadIdx.x;
    if (i >= n4) return;
    float4 v = reinterpret_cast<const float4*>(in)[i];
    reinterpret_cast<ushort4*>(outp)[i] = make_ushort4(
        __half_as_ushort(__float2half_rn(v.x)),
        __half_as_ushort(__float2half_rn(v.y)),
        __half_as_ushort(__float2half_rn(v.z)),
        __half_as_ushort(__float2half_rn(v.w)));
}

// ---------------------------------------------------------------------------
// Helpers (portable to base sm_103: mma.sync + cp.async + ldmatrix)
// ---------------------------------------------------------------------------
__device__ __forceinline__ uint32_t smem_u32(const void* p) {
    uint32_t a;
    asm("{ .reg .u64 t; cvta.to.shared.u64 t, %1; cvt.u32.u64 %0, t; }"
        : "=r"(a) : "l"(p));
    return a;
}
__device__ __forceinline__ void cp16(uint32_t dst, const void* src, bool pred) {
    int sz = pred ? 16 : 0;
    asm volatile("cp.async.cg.shared.global [%0], [%1], 16, %2;"
                 :: "r"(dst), "l"(src), "r"(sz) : "memory");
}
__device__ __forceinline__ void mma16816(float* c, const uint32_t* a,
                                         const uint32_t* b) {
    asm volatile(
        "mma.sync.aligned.m16n8k16.row.col.f32.f16.f16.f32 "
        "{%0,%1,%2,%3}, {%4,%5,%6,%7}, {%8,%9}, {%0,%1,%2,%3};"
        : "+f"(c[0]), "+f"(c[1]), "+f"(c[2]), "+f"(c[3])
        : "r"(a[0]), "r"(a[1]), "r"(a[2]), "r"(a[3]), "r"(b[0]), "r"(b[1]));
}
__device__ __forceinline__ void ldsm4(uint32_t* r, uint32_t addr) {
    asm volatile("ldmatrix.sync.aligned.m8n8.x4.shared.b16 {%0,%1,%2,%3}, [%4];"
                 : "=r"(r[0]), "=r"(r[1]), "=r"(r[2]), "=r"(r[3]) : "r"(addr));
}

constexpr int BM = 128, BN = 128, BK = 32;
constexpr int ROWB  = BK * 2;            // 64 bytes per smem row
constexpr int ARR   = BM * ROWB;         // 8KB per array (Ah/Al/Bf)
constexpr int STAGE = 3 * ARR;           // 24KB
constexpr int NST   = 3;
constexpr int SMEM_TOTAL = NST * STAGE;  // 72KB -> 2 CTAs/SM
constexpr int THREADS = 128;             // 4 warps, 2x2, 64x64 warp tiles

// swizzle: 16B slot XOR'd by (row>>1)&3 — conflict-free for ldmatrix 8-row
// groups. XOR applied to the FINAL column (incl. K-half offset): no carry.
__device__ __forceinline__ uint32_t swz_off(uint32_t row, uint32_t col) {
    return row * ROWB + (col ^ (((row >> 1) & 3u) << 4));
}

// ---------------------------------------------------------------------------
// fp16x2 GEMM on mma.sync + ldmatrix:
//   Out[m,n] = epi( (Ah+Al)[m,:].Wf[n,:] + bias )   -- 2 MMAs per fragment
// Epilogue: +bias, relu, *scale, += (addH+addL), fp32 store OR fp16 hi/lo split.
// GATE: rows gathered/scattered via g_perm segment blockIdx.z, W offset by gate.
// ---------------------------------------------------------------------------
template<bool GATE>
__global__ __launch_bounds__(THREADS, 2)
void mma_gemm(const __half* __restrict__ Ah,
              const __half* __restrict__ Al,
              const __half* __restrict__ Wf_,
              const float* __restrict__ bias_,
              float* __restrict__ outF,
              __half* __restrict__ outH, __half* __restrict__ outL,
              const __half* __restrict__ addH,
              const __half* __restrict__ addL,
              int Nout, int K, int do_relu, float scale)
{
    extern __shared__ char smem[];
    const uint32_t sb = smem_u32(smem);
    const int tid = threadIdx.x, wid = tid >> 5, lid = tid & 31;

    int rowStart, rowValid;
    const __half* Wf = Wf_;
    const float* bp = bias_;
    if (GATE) {
        int g = blockIdx.z;
        int s0 = g_off[g], s1 = g_off[g + 1];
        rowStart = s0 + blockIdx.y * BM;
        if (rowStart >= s1) return;
        rowValid = min(BM, s1 - rowStart);
        Wf += (size_t)g * Nout * K;
        if (bp) bp += (size_t)g * Nout;
    } else {
        rowStart = blockIdx.y * BM;
        rowValid = BM;
    }
    const int cb = blockIdx.x * BN;

    // ---- cp.async mapping: 128 threads x 4 iters cover 512 chunks per array
    const __half* pAh[4];
    const __half* pAl[4];
    const __half* pBf[4];
    bool vA[4];
    uint32_t dOf[4];
#pragma unroll
    for (int i = 0; i < 4; i++) {
        int cid = tid + i * THREADS;
        int r = cid >> 2, c16 = cid & 3;
        dOf[i] = swz_off(r, c16 * 16);
        int ar;
        if (GATE) { ar = (r < rowValid) ? g_perm[rowStart + r] : -1; }
        else      { ar = rowStart + r; }
        vA[i] = ar >= 0;
        size_t aoff = (vA[i] ? (size_t)ar * K : 0) + c16 * 8;
        pAh[i] = Ah + aoff;
        pAl[i] = Al + aoff;
        pBf[i] = Wf + (size_t)(cb + r) * K + c16 * 8;
    }

    const int T = K / BK;
    auto load_tile = [&](int kt) {
        uint32_t st = sb + (kt % NST) * STAGE;
        int ke = kt * BK;
#pragma unroll
        for (int i = 0; i < 4; i++) {
            cp16(st + 0 * ARR + dOf[i], pAh[i] + ke, vA[i]);
            cp16(st + 1 * ARR + dOf[i], pAl[i] + ke, vA[i]);
            cp16(st + 2 * ARR + dOf[i], pBf[i] + ke, true);
        }
        asm volatile("cp.async.commit_group;" ::: "memory");
    };

    float acc[4][8][4];
#pragma unroll
    for (int a = 0; a < 4; a++)
#pragma unroll
        for (int b = 0; b < 8; b++)
#pragma unroll
            for (int c = 0; c < 4; c++) acc[a][b][c] = 0.f;

    // warp tiling: 2x2 warps, 64x64 per warp
    const int wm = (wid >> 1) * 64;
    const int wn = (wid & 1) * 64;
    const int lg = lid >> 3, l7 = lid & 7;

    // ldmatrix lane components: row offset + mask separate from column so the
    // K-half offset is added BEFORE the swizzle XOR (no carry into row bits).
    uint32_t rowA[4], mskA[4], rowB[4], mskB[4];
    const uint32_t colA = (uint32_t)(lg >> 1) << 4;
    const uint32_t colB = (uint32_t)(lg & 1) << 4;
#pragma unroll
    for (int mt = 0; mt < 4; mt++) {
        uint32_t row = wm + mt * 16 + ((lg & 1) << 3) + l7;
        rowA[mt] = row * ROWB;
        mskA[mt] = ((row >> 1) & 3u) << 4;
    }
#pragma unroll
    for (int np = 0; np < 4; np++) {
        uint32_t row = wn + np * 16 + ((lg >> 1) << 3) + l7;
        rowB[np] = row * ROWB;
        mskB[np] = ((row >> 1) & 3u) << 4;
    }

    load_tile(0);
    load_tile(1);

    for (int kt = 0; kt < T; kt++) {
        if (kt < T - 1) asm volatile("cp.async.wait_group 1;" ::: "memory");
        else            asm volatile("cp.async.wait_group 0;" ::: "memory");
        __syncthreads();
        if (kt + 2 < T) load_tile(kt + 2);

        const uint32_t S = sb + (kt % NST) * STAGE;
#pragma unroll
        for (int kh = 0; kh < 2; kh++) {
            const uint32_t kof = kh * 32;
            uint32_t ah[4][4], al[4][4], bf[4][4];
#pragma unroll
            for (int mt = 0; mt < 4; mt++) {
                uint32_t off = rowA[mt] + ((colA + kof) ^ mskA[mt]);
                ldsm4(ah[mt], S + 0 * ARR + off);
                ldsm4(al[mt], S + 1 * ARR + off);
            }
#pragma unroll
            for (int np = 0; np < 4; np++) {
                uint32_t off = rowB[np] + ((colB + kof) ^ mskB[np]);
                ldsm4(bf[np], S + 2 * ARR + off);
            }
#pragma unroll
            for (int mt = 0; mt < 4; mt++) {
#pragma unroll
                for (int np = 0; np < 4; np++) {
                    // np covers nt = 2np (regs 0,1) and nt = 2np+1 (regs 2,3)
                    mma16816(acc[mt][2 * np],     ah[mt], &bf[np][0]);
                    mma16816(acc[mt][2 * np],     al[mt], &bf[np][0]);
                    mma16816(acc[mt][2 * np + 1], ah[mt], &bf[np][2]);
                    mma16816(acc[mt][2 * np + 1], al[mt], &bf[np][2]);
                }
            }
        }
    }

    // ------------------------------- epilogue ------------------------------
    const int gr = lid >> 2;
#pragma unroll
    for (int mt = 0; mt < 4; mt++) {
#pragma unroll
        for (int half = 0; half < 2; half++) {
            const int rloc = wm + mt * 16 + gr + half * 8;
            int grow;
            bool valid = true;
            if (GATE) {
                valid = (rloc < rowValid);
                grow = valid ? g_perm[rowStart + rloc] : 0;
            } else {
                grow = rowStart + rloc;
            }
            if (!valid) continue;
#pragma unroll
            for (int nt = 0; nt < 8; nt++) {
                const int col = cb + wn + nt * 8 + (lid & 3) * 2;
                float v0 = acc[mt][nt][half * 2 + 0];
                float v1 = acc[mt][nt][half * 2 + 1];
                if (bp) {
                    float2 bb = *(const float2*)(bp + col);
                    v0 += bb.x; v1 += bb.y;
                }
                if (do_relu) { v0 = fmaxf(v0, 0.f); v1 = fmaxf(v1, 0.f); }
                v0 *= scale; v1 *= scale;
                const size_t rb = (size_t)grow * Nout + col;
                if (addH) {
                    uint32_t uh = *(const uint32_t*)(addH + rb);
                    uint32_t ul = *(const uint32_t*)(addL + rb);
                    float2 fh = __half22float2(
                        *reinterpret_cast<__half2*>(&uh));
                    float2 fl = __half22float2(
                        *reinterpret_cast<__half2*>(&ul));
                    v0 += fh.x + fl.x; v1 += fh.y + fl.y;
                }
                if (outF) {
                    *(float2*)(outF + rb) = make_float2(v0, v1);
                } else {
                    __half h0 = __float2half_rn(v0);
                    __half h1 = __float2half_rn(v1);
                    __half l0 = __float2half_rn(v0 - __half2float(h0));
                    __half l1 = __float2half_rn(v1 - __half2float(h1));
                    uint32_t ph = (uint32_t)__half_as_ushort(h0) |
                                  ((uint32_t)__half_as_ushort(h1) << 16);
                    uint32_t pl = (uint32_t)__half_as_ushort(l0) |
                                  ((uint32_t)__half_as_ushort(l1) << 16);
                    *(uint32_t*)(outH + rb) = ph;
                    *(uint32_t*)(outL + rb) = pl;
                }
            }
        }
    }
}

// ---------------------------------------------------------------------------
extern "C" void kernel_launch(void* const* d_in, const int* in_sizes, int n_in,
                              void* d_out, int out_size) {
    const float* x   = (const float*)d_in[0];
    const int*   gid = (const int*)  d_in[1];
    const float* W1  = (const float*)d_in[2];
    const float* b1  = (const float*)d_in[3];
    const float* W2  = (const float*)d_in[4];
    const float* b2  = (const float*)d_in[5];
    const float* W3  = (const float*)d_in[6];
    float* out = (float*)d_out;

    __half *xh, *xl, *w1f, *w2f, *w3f, *sh, *sl, *h2h, *h2l;
    cudaGetSymbolAddress((void**)&xh,  g_xh);  cudaGetSymbolAddress((void**)&xl,  g_xl);
    cudaGetSymbolAddress((void**)&w1f, g_W1f);
    cudaGetSymbolAddress((void**)&w2f, g_W2f);
    cudaGetSymbolAddress((void**)&w3f, g_W3f);
    cudaGetSymbolAddress((void**)&sh,  g_sh);  cudaGetSymbolAddress((void**)&sl,  g_sl);
    cudaGetSymbolAddress((void**)&h2h, g_h2h); cudaGetSymbolAddress((void**)&h2l, g_h2l);

    cudaFuncSetAttribute((const void*)mma_gemm<true>,
                         cudaFuncAttributeMaxDynamicSharedMemorySize, SMEM_TOTAL);
    cudaFuncSetAttribute((const void*)mma_gemm<false>,
                         cudaFuncAttributeMaxDynamicSharedMemorySize, SMEM_TOTAL);

    sort_gates<<<1, 256>>>(gid);

    auto nblk = [](size_t elems) { return (int)((elems / 4 + 255) / 256); };
    split_f32h<<<nblk((size_t)NROWS * INDIM), 256>>>(x, xh, xl, NROWS * INDIM / 4);
    conv_f32h<<<nblk((size_t)W1R * INDIM),   256>>>(W1, w1f, (int)((size_t)W1R * INDIM / 4));
    conv_f32h<<<nblk((size_t)DDIM * TWOD),   256>>>(W2, w2f, DDIM * TWOD / 4);
    conv_f32h<<<nblk((size_t)OUTDIM * DDIM), 256>>>(W3, w3f, OUTDIM * DDIM / 4);

    // L1 gate blocks: s = 0.9*relu(x @ W1_g^T + b1_g), rows scattered via perm
    mma_gemm<true><<<dim3(TWOD / BN, NROWS / BM, NGATE), THREADS, SMEM_TOTAL>>>(
        xh, xl, w1f, b1,
        nullptr, sh, sl, nullptr, nullptr,
        TWOD, INDIM, /*relu=*/1, /*scale=*/0.9f);

    // L1 shared block: s += relu(x @ W1_sh^T + b1_sh)  (adds prior s, re-splits)
    mma_gemm<false><<<dim3(TWOD / BN, NROWS / BM), THREADS, SMEM_TOTAL>>>(
        xh, xl,
        w1f + (size_t)NGATE * TWOD * INDIM,
        b1 + (size_t)NGATE * TWOD,
        nullptr, sh, sl, sh, sl,
        TWOD, INDIM, /*relu=*/1, /*scale=*/1.0f);

    // L2: h2 = relu(s @ W2^T + b2)
    mma_gemm<false><<<dim3(DDIM / BN, NROWS / BM), THREADS, SMEM_TOTAL>>>(
        sh, sl, w2f, b2,
        nullptr, h2h, h2l, nullptr, nullptr,
        DDIM, TWOD, /*relu=*/1, /*scale=*/1.0f);

    // L3: out = h2 @ W3^T  (fp32 store)
    mma_gemm<false><<<dim3(OUTDIM / BN, NROWS / BM), THREADS, SMEM_TOTAL>>>(
        h2h, h2l, w3f, nullptr,
        out, nullptr, nullptr, nullptr, nullptr,
        OUTDIM, DDIM, /*relu=*/0, /*scale=*/1.0f);
}

// round 8
// speedup vs baseline: 4.0468x; 1.0023x over previous
#include <cuda_runtime.h>
#include <cuda_fp16.h>
#include <cstdint>

#define NROWS 4096
#define INDIM 1024
#define DDIM  2048
#define TWOD  4096
#define NGATE 8
#define OUTDIM 1024
#define W1R   (2*(1+NGATE)*DDIM)   // 36864

// ---------------------------------------------------------------------------
// Device scratch (allocation-free rule: __device__ globals)
// A-side operands are split fp16 hi/lo; weights are single fp16.
// ---------------------------------------------------------------------------
__device__ __half g_xh [(size_t)NROWS * INDIM];
__device__ __half g_xl [(size_t)NROWS * INDIM];
__device__ __half g_W1f[(size_t)W1R   * INDIM];
__device__ __half g_W2f[(size_t)DDIM  * TWOD];
__device__ __half g_W3f[(size_t)OUTDIM* DDIM];
__device__ __half g_sh [(size_t)NROWS * TWOD];
__device__ __half g_sl [(size_t)NROWS * TWOD];
__device__ __half g_h2h[(size_t)NROWS * DDIM];
__device__ __half g_h2l[(size_t)NROWS * DDIM];
__device__ int g_perm[NROWS];
__device__ int g_off[NGATE + 1];

// ---------------------------------------------------------------------------
__global__ void sort_gates(const int* __restrict__ gate_ids) {
    __shared__ int cnt[NGATE];
    __shared__ int base[NGATE];
    int t = threadIdx.x;
    if (t < NGATE) cnt[t] = 0;
    __syncthreads();
    for (int i = t; i < NROWS; i += blockDim.x)
        atomicAdd(&cnt[gate_ids[i]], 1);
    __syncthreads();
    if (t == 0) {
        int a = 0;
        for (int g = 0; g < NGATE; g++) { base[g] = a; g_off[g] = a; a += cnt[g]; }
        g_off[NGATE] = a;
    }
    __syncthreads();
    for (int i = t; i < NROWS; i += blockDim.x) {
        int g = gate_ids[i];
        int p = atomicAdd(&base[g], 1);
        g_perm[p] = i;
    }
}

// ---------------------------------------------------------------------------
// fp32 -> (fp16 hi, fp16 lo) exact split (activations)
// ---------------------------------------------------------------------------
__global__ __launch_bounds__(256) void split_f32h(
    const float* __restrict__ in,
    __half* __restrict__ hi, __half* __restrict__ lo, int n4)
{
    int i = blockIdx.x * 256 + threadIdx.x;
    if (i >= n4) return;
    float4 v = reinterpret_cast<const float4*>(in)[i];
    __half h0 = __float2half_rn(v.x);
    __half h1 = __float2half_rn(v.y);
    __half h2 = __float2half_rn(v.z);
    __half h3 = __float2half_rn(v.w);
    __half l0 = __float2half_rn(v.x - __half2float(h0));
    __half l1 = __float2half_rn(v.y - __half2float(h1));
    __half l2 = __float2half_rn(v.z - __half2float(h2));
    __half l3 = __float2half_rn(v.w - __half2float(h3));
    reinterpret_cast<ushort4*>(hi)[i] = make_ushort4(
        __half_as_ushort(h0), __half_as_ushort(h1),
        __half_as_ushort(h2), __half_as_ushort(h3));
    reinterpret_cast<ushort4*>(lo)[i] = make_ushort4(
        __half_as_ushort(l0), __half_as_ushort(l1),
        __half_as_ushort(l2), __half_as_ushort(l3));
}

// fp32 -> fp16 (weights, single rounding)
__global__ __launch_bounds__(256) void conv_f32h(
    const float* __restrict__ in, __half* __restrict__ outp, int n4)
{
    int i = blockIdx.x * 256 + threadIdx.x;
    if (i >= n4) return;
    float4 v = reinterpret_cast<const float4*>(in)[i];
    reinterpret_cast<ushort4*>(outp)[i] = make_ushort4(
        __half_as_ushort(__float2half_rn(v.x)),
        __half_as_ushort(__float2half_rn(v.y)),
        __half_as_ushort(__float2half_rn(v.z)),
        __half_as_ushort(__float2half_rn(v.w)));
}

// ---------------------------------------------------------------------------
// Helpers (portable to base sm_103: mma.sync + cp.async + ldmatrix)
// ---------------------------------------------------------------------------
__device__ __forceinline__ uint32_t smem_u32(const void* p) {
    uint32_t a;
    asm("{ .reg .u64 t; cvta.to.shared.u64 t, %1; cvt.u32.u64 %0, t; }"
        : "=r"(a) : "l"(p));
    return a;
}
__device__ __forceinline__ void cp16(uint32_t dst, const void* src, bool pred) {
    int sz = pred ? 16 : 0;
    asm volatile("cp.async.cg.shared.global [%0], [%1], 16, %2;"
                 :: "r"(dst), "l"(src), "r"(sz) : "memory");
}
__device__ __forceinline__ void mma16816(float* c, const uint32_t* a,
                                         const uint32_t* b) {
    asm volatile(
        "mma.sync.aligned.m16n8k16.row.col.f32.f16.f16.f32 "
        "{%0,%1,%2,%3}, {%4,%5,%6,%7}, {%8,%9}, {%0,%1,%2,%3};"
        : "+f"(c[0]), "+f"(c[1]), "+f"(c[2]), "+f"(c[3])
        : "r"(a[0]), "r"(a[1]), "r"(a[2]), "r"(a[3]), "r"(b[0]), "r"(b[1]));
}
__device__ __forceinline__ void ldsm4(uint32_t* r, uint32_t addr) {
    asm volatile("ldmatrix.sync.aligned.m8n8.x4.shared.b16 {%0,%1,%2,%3}, [%4];"
                 : "=r"(r[0]), "=r"(r[1]), "=r"(r[2]), "=r"(r[3]) : "r"(addr));
}

constexpr int BM = 128, BN = 128, BK = 32;
constexpr int ROWB  = BK * 2;            // 64 bytes per smem row
constexpr int ARR   = BM * ROWB;         // 8KB per array (Ah/Al/Bf)
constexpr int STAGE = 3 * ARR;           // 24KB
constexpr int NST   = 3;
constexpr int SMEM_TOTAL = NST * STAGE;  // 72KB -> 2 CTAs/SM
constexpr int THREADS = 128;             // 4 warps, 2x2, 64x64 warp tiles

// swizzle: 16B slot XOR'd by (row>>1)&3 — conflict-free for ldmatrix 8-row
// groups. XOR applied to the FINAL column (incl. K-half offset): no carry.
__device__ __forceinline__ uint32_t swz_off(uint32_t row, uint32_t col) {
    return row * ROWB + (col ^ (((row >> 1) & 3u) << 4));
}

// ---------------------------------------------------------------------------
// fp16x2 GEMM on mma.sync + ldmatrix:
//   Out[m,n] = epi( (Ah+Al)[m,:].Wf[n,:] + bias )   -- 2 MMAs per fragment
// Epilogue: +bias, relu, *scale, += (addH+addL), fp32 store OR fp16 hi/lo split.
// GATE: rows gathered/scattered via g_perm segment blockIdx.z, W offset by gate.
// ---------------------------------------------------------------------------
template<bool GATE>
__global__ __launch_bounds__(THREADS, 2)
void mma_gemm(const __half* __restrict__ Ah,
              const __half* __restrict__ Al,
              const __half* __restrict__ Wf_,
              const float* __restrict__ bias_,
              float* __restrict__ outF,
              __half* __restrict__ outH, __half* __restrict__ outL,
              const __half* __restrict__ addH,
              const __half* __restrict__ addL,
              int Nout, int K, int do_relu, float scale)
{
    extern __shared__ char smem[];
    const uint32_t sb = smem_u32(smem);
    const int tid = threadIdx.x, wid = tid >> 5, lid = tid & 31;

    int rowStart, rowValid;
    const __half* Wf = Wf_;
    const float* bp = bias_;
    if (GATE) {
        int g = blockIdx.z;
        int s0 = g_off[g], s1 = g_off[g + 1];
        rowStart = s0 + blockIdx.y * BM;
        if (rowStart >= s1) return;
        rowValid = min(BM, s1 - rowStart);
        Wf += (size_t)g * Nout * K;
        if (bp) bp += (size_t)g * Nout;
    } else {
        rowStart = blockIdx.y * BM;
        rowValid = BM;
    }
    const int cb = blockIdx.x * BN;

    // ---- cp.async mapping: 128 threads x 4 iters cover 512 chunks per array
    const __half* pAh[4];
    const __half* pAl[4];
    const __half* pBf[4];
    bool vA[4];
    uint32_t dOf[4];
#pragma unroll
    for (int i = 0; i < 4; i++) {
        int cid = tid + i * THREADS;
        int r = cid >> 2, c16 = cid & 3;
        dOf[i] = swz_off(r, c16 * 16);
        int ar;
        if (GATE) { ar = (r < rowValid) ? g_perm[rowStart + r] : -1; }
        else      { ar = rowStart + r; }
        vA[i] = ar >= 0;
        size_t aoff = (vA[i] ? (size_t)ar * K : 0) + c16 * 8;
        pAh[i] = Ah + aoff;
        pAl[i] = Al + aoff;
        pBf[i] = Wf + (size_t)(cb + r) * K + c16 * 8;
    }

    const int T = K / BK;
    auto load_tile = [&](int kt) {
        uint32_t st = sb + (kt % NST) * STAGE;
        int ke = kt * BK;
#pragma unroll
        for (int i = 0; i < 4; i++) {
            cp16(st + 0 * ARR + dOf[i], pAh[i] + ke, vA[i]);
            cp16(st + 1 * ARR + dOf[i], pAl[i] + ke, vA[i]);
            cp16(st + 2 * ARR + dOf[i], pBf[i] + ke, true);
        }
        asm volatile("cp.async.commit_group;" ::: "memory");
    };

    float acc[4][8][4];
#pragma unroll
    for (int a = 0; a < 4; a++)
#pragma unroll
        for (int b = 0; b < 8; b++)
#pragma unroll
            for (int c = 0; c < 4; c++) acc[a][b][c] = 0.f;

    // warp tiling: 2x2 warps, 64x64 per warp
    const int wm = (wid >> 1) * 64;
    const int wn = (wid & 1) * 64;
    const int lg = lid >> 3, l7 = lid & 7;

    // ldmatrix lane components: row offset + mask separate from column so the
    // K-half offset is added BEFORE the swizzle XOR (no carry into row bits).
    uint32_t rowA[4], mskA[4], rowB[4], mskB[4];
    const uint32_t colA = (uint32_t)(lg >> 1) << 4;
    const uint32_t colB = (uint32_t)(lg & 1) << 4;
#pragma unroll
    for (int mt = 0; mt < 4; mt++) {
        uint32_t row = wm + mt * 16 + ((lg & 1) << 3) + l7;
        rowA[mt] = row * ROWB;
        mskA[mt] = ((row >> 1) & 3u) << 4;
    }
#pragma unroll
    for (int np = 0; np < 4; np++) {
        uint32_t row = wn + np * 16 + ((lg >> 1) << 3) + l7;
        rowB[np] = row * ROWB;
        mskB[np] = ((row >> 1) & 3u) << 4;
    }

    load_tile(0);
    load_tile(1);

    for (int kt = 0; kt < T; kt++) {
        if (kt < T - 1) asm volatile("cp.async.wait_group 1;" ::: "memory");
        else            asm volatile("cp.async.wait_group 0;" ::: "memory");
        __syncthreads();
        if (kt + 2 < T) load_tile(kt + 2);

        const uint32_t S = sb + (kt % NST) * STAGE;
#pragma unroll
        for (int kh = 0; kh < 2; kh++) {
            const uint32_t kof = kh * 32;
            uint32_t ah[4][4], al[4][4], bf[4][4];
#pragma unroll
            for (int mt = 0; mt < 4; mt++) {
                uint32_t off = rowA[mt] + ((colA + kof) ^ mskA[mt]);
                ldsm4(ah[mt], S + 0 * ARR + off);
                ldsm4(al[mt], S + 1 * ARR + off);
            }
#pragma unroll
            for (int np = 0; np < 4; np++) {
                uint32_t off = rowB[np] + ((colB + kof) ^ mskB[np]);
                ldsm4(bf[np], S + 2 * ARR + off);
            }
#pragma unroll
            for (int mt = 0; mt < 4; mt++) {
#pragma unroll
                for (int np = 0; np < 4; np++) {
                    // np covers nt = 2np (regs 0,1) and nt = 2np+1 (regs 2,3)
                    mma16816(acc[mt][2 * np],     ah[mt], &bf[np][0]);
                    mma16816(acc[mt][2 * np],     al[mt], &bf[np][0]);
                    mma16816(acc[mt][2 * np + 1], ah[mt], &bf[np][2]);
                    mma16816(acc[mt][2 * np + 1], al[mt], &bf[np][2]);
                }
            }
        }
    }

    // ------------------------------- epilogue ------------------------------
    const int gr = lid >> 2;
#pragma unroll
    for (int mt = 0; mt < 4; mt++) {
#pragma unroll
        for (int half = 0; half < 2; half++) {
            const int rloc = wm + mt * 16 + gr + half * 8;
            int grow;
            bool valid = true;
            if (GATE) {
                valid = (rloc < rowValid);
                grow = valid ? g_perm[rowStart + rloc] : 0;
            } else {
                grow = rowStart + rloc;
            }
            if (!valid) continue;
#pragma unroll
            for (int nt = 0; nt < 8; nt++) {
                const int col = cb + wn + nt * 8 + (lid & 3) * 2;
                float v0 = acc[mt][nt][half * 2 + 0];
                float v1 = acc[mt][nt][half * 2 + 1];
                if (bp) {
                    float2 bb = *(const float2*)(bp + col);
                    v0 += bb.x; v1 += bb.y;
                }
                if (do_relu) { v0 = fmaxf(v0, 0.f); v1 = fmaxf(v1, 0.f); }
                v0 *= scale; v1 *= scale;
                const size_t rb = (size_t)grow * Nout + col;
                if (addH) {
                    uint32_t uh = *(const uint32_t*)(addH + rb);
                    uint32_t ul = *(const uint32_t*)(addL + rb);
                    float2 fh = __half22float2(
                        *reinterpret_cast<__half2*>(&uh));
                    float2 fl = __half22float2(
                        *reinterpret_cast<__half2*>(&ul));
                    v0 += fh.x + fl.x; v1 += fh.y + fl.y;
                }
                if (outF) {
                    *(float2*)(outF + rb) = make_float2(v0, v1);
                } else {
                    __half h0 = __float2half_rn(v0);
                    __half h1 = __float2half_rn(v1);
                    __half l0 = __float2half_rn(v0 - __half2float(h0));
                    __half l1 = __float2half_rn(v1 - __half2float(h1));
                    uint32_t ph = (uint32_t)__half_as_ushort(h0) |
                                  ((uint32_t)__half_as_ushort(h1) << 16);
                    uint32_t pl = (uint32_t)__half_as_ushort(l0) |
                                  ((uint32_t)__half_as_ushort(l1) << 16);
                    *(uint32_t*)(outH + rb) = ph;
                    *(uint32_t*)(outL + rb) = pl;
                }
            }
        }
    }
}

// ---------------------------------------------------------------------------
extern "C" void kernel_launch(void* const* d_in, const int* in_sizes, int n_in,
                              void* d_out, int out_size) {
    const float* x   = (const float*)d_in[0];
    const int*   gid = (const int*)  d_in[1];
    const float* W1  = (const float*)d_in[2];
    const float* b1  = (const float*)d_in[3];
    const float* W2  = (const float*)d_in[4];
    const float* b2  = (const float*)d_in[5];
    const float* W3  = (const float*)d_in[6];
    float* out = (float*)d_out;

    __half *xh, *xl, *w1f, *w2f, *w3f, *sh, *sl, *h2h, *h2l;
    cudaGetSymbolAddress((void**)&xh,  g_xh);  cudaGetSymbolAddress((void**)&xl,  g_xl);
    cudaGetSymbolAddress((void**)&w1f, g_W1f);
    cudaGetSymbolAddress((void**)&w2f, g_W2f);
    cudaGetSymbolAddress((void**)&w3f, g_W3f);
    cudaGetSymbolAddress((void**)&sh,  g_sh);  cudaGetSymbolAddress((void**)&sl,  g_sl);
    cudaGetSymbolAddress((void**)&h2h, g_h2h); cudaGetSymbolAddress((void**)&h2l, g_h2l);

    cudaFuncSetAttribute((const void*)mma_gemm<true>,
                         cudaFuncAttributeMaxDynamicSharedMemorySize, SMEM_TOTAL);
    cudaFuncSetAttribute((const void*)mma_gemm<false>,
                         cudaFuncAttributeMaxDynamicSharedMemorySize, SMEM_TOTAL);

    sort_gates<<<1, 256>>>(gid);

    auto nblk = [](size_t elems) { return (int)((elems / 4 + 255) / 256); };
    split_f32h<<<nblk((size_t)NROWS * INDIM), 256>>>(x, xh, xl, NROWS * INDIM / 4);
    conv_f32h<<<nblk((size_t)W1R * INDIM),   256>>>(W1, w1f, (int)((size_t)W1R * INDIM / 4));
    conv_f32h<<<nblk((size_t)DDIM * TWOD),   256>>>(W2, w2f, DDIM * TWOD / 4);
    conv_f32h<<<nblk((size_t)OUTDIM * DDIM), 256>>>(W3, w3f, OUTDIM * DDIM / 4);

    // L1 gate blocks: s = 0.9*relu(x @ W1_g^T + b1_g), rows scattered via perm
    mma_gemm<true><<<dim3(TWOD / BN, NROWS / BM, NGATE), THREADS, SMEM_TOTAL>>>(
        xh, xl, w1f, b1,
        nullptr, sh, sl, nullptr, nullptr,
        TWOD, INDIM, /*relu=*/1, /*scale=*/0.9f);

    // L1 shared block: s += relu(x @ W1_sh^T + b1_sh)  (adds prior s, re-splits)
    mma_gemm<false><<<dim3(TWOD / BN, NROWS / BM), THREADS, SMEM_TOTAL>>>(
        xh, xl,
        w1f + (size_t)NGATE * TWOD * INDIM,
        b1 + (size_t)NGATE * TWOD,
        nullptr, sh, sl, sh, sl,
        TWOD, INDIM, /*relu=*/1, /*scale=*/1.0f);

    // L2: h2 = relu(s @ W2^T + b2)
    mma_gemm<false><<<dim3(DDIM / BN, NROWS / BM), THREADS, SMEM_TOTAL>>>(
        sh, sl, w2f, b2,
        nullptr, h2h, h2l, nullptr, nullptr,
        DDIM, TWOD, /*relu=*/1, /*scale=*/1.0f);

    // L3: out = h2 @ W3^T  (fp32 store)
    mma_gemm<false><<<dim3(OUTDIM / BN, NROWS / BM), THREADS, SMEM_TOTAL>>>(
        h2h, h2l, w3f, nullptr,
        out, nullptr, nullptr, nullptr, nullptr,
        OUTDIM, DDIM, /*relu=*/0, /*scale=*/1.0f);
}